// round 8
// baseline (speedup 1.0000x reference)
#include <cuda_runtime.h>
#include <cstdint>

// USR_EMB: out[row] = emb[searchsorted(userlist, x[row])], 64 f32/row.
// Status: ~98% of the measured LTS cap (~11.3TB/s @NAT) — 420MB must cross
// L2 (210MB gather-hit reads + 210MB writes); hard floor ~37us. R8 keeps the
// winning R7 structure (warp-cooperative indexing, burst of 8 .cg gathers,
// 8 .cs streaming stores) and shaves issue overhead: hoisted full-warp fast
// path (no per-store predicates), no explicit __syncwarp (shfl_sync
// converges), 512-thread blocks for wave balance.

static constexpr int EMB = 64;
static constexpr int CPR = EMB / 4;  // 16 float4 chunks per row
static constexpr int RPW = 16;       // rows per warp

__global__ void __launch_bounds__(512) usr_emb_kernel(
    const int* __restrict__ x,
    const int* __restrict__ userlist,
    const float4* __restrict__ emb,      // [emb_rows][16] float4
    float4* __restrict__ out,            // [n_rows][16] float4
    int n_rows, int n_userlist, int emb_rows)
{
    int warpId = (blockIdx.x * blockDim.x + threadIdx.x) >> 5;
    int lane   = threadIdx.x & 31;
    int group  = lane >> 4;              // which 8-row half this thread moves
    int chunk  = lane & 15;              // float4 within row
    int wrow0  = warpId * RPW;
    if (wrow0 >= n_rows) return;

    bool full = (wrow0 + RPW) <= n_rows;

    // ---- Cooperative index computation: lanes 0-15, one row each ----
    int myIdx = 0;
    if (lane < RPW) {
        int r = wrow0 + lane;
        int u = (full || r < n_rows) ? __ldcs(&x[r]) : 0;  // coalesced 64B
        // Fast path: userlist = [-1, 0..N-1] => searchsorted(u) = u+1.
        // Verified against data; binary-search fallback for generality.
        int i = u + 1;
        bool ok = (i >= 1) && (i < n_userlist)
                  && (__ldg(&userlist[i]) == u)
                  && (__ldg(&userlist[i - 1]) < u);
        if (!ok) {
            int lo = 0, hi = n_userlist;
            while (lo < hi) {
                int mid = (lo + hi) >> 1;
                if (__ldg(&userlist[mid]) < u) lo = mid + 1; else hi = mid;
            }
            i = lo;
        }
        if (i >= emb_rows) i = emb_rows - 1;
        if (i < 0) i = 0;
        myIdx = i;
    }

    // shfl_sync with full mask converges the warp; no explicit __syncwarp.
    int idx[8];
#pragma unroll
    for (int k = 0; k < 8; k++)
        idx[k] = __shfl_sync(0xffffffffu, myIdx, group * 8 + k);

    int rowBase = wrow0 + group * 8;

    if (full) {
        // ---- 8 independent gathers in one burst (MLP=8), L2-hit, no L1 ----
        float4 v[8];
#pragma unroll
        for (int k = 0; k < 8; k++)
            v[k] = __ldcg(&emb[(size_t)idx[k] * CPR + chunk]);

        // ---- 8 unpredicated coalesced streaming stores ----
#pragma unroll
        for (int k = 0; k < 8; k++)
            __stcs(&out[(size_t)(rowBase + k) * CPR + chunk], v[k]);
    } else {
        // Guarded tail path (generic shapes).
#pragma unroll
        for (int k = 0; k < 8; k++) {
            int r = rowBase + k;
            if (r < n_rows) {
                float4 v = __ldcg(&emb[(size_t)idx[k] * CPR + chunk]);
                __stcs(&out[(size_t)r * CPR + chunk], v);
            }
        }
    }
}

extern "C" void kernel_launch(void* const* d_in, const int* in_sizes, int n_in,
                              void* d_out, int out_size)
{
    const int*   x        = (const int*)d_in[0];    // [B*H] int32
    const int*   userlist = (const int*)d_in[1];    // [N+1] int32
    const float* emb      = (const float*)d_in[2];  // [(N+1)*64] f32

    int n_rows     = in_sizes[0];          // 819200
    int n_userlist = in_sizes[1];          // 100001
    int emb_rows   = in_sizes[2] / EMB;    // 100001

    int n_warps = (n_rows + RPW - 1) / RPW;          // 51200
    long long total_threads = (long long)n_warps * 32;
    int block = 512;
    int grid  = (int)((total_threads + block - 1) / block);  // 3200

    usr_emb_kernel<<<grid, block>>>(x, userlist, (const float4*)emb,
                                    (float4*)d_out, n_rows, n_userlist, emb_rows);
}